// round 4
// baseline (speedup 1.0000x reference)
#include <cuda_runtime.h>
#include <cstdint>

#define NNODES 768
#define NFACES 256
#define NTOT   1024
#define E0     6144
#define EF     1536
#define ETOT   9216
#define C      64
#define COLCAP 64
#define NKT    16
#define HSTR   68
#define CONCAP 1024

// ---------------- device scratch ----------------
// unified feature table: rows [0,1024) = node_all, rows [1024,7168) = edge conn
__device__ float g_feat[(NTOT + E0) * C];
__device__ float g_adjn[NTOT * NTOT];
__device__ float g_dinv[NTOT];
__device__ float g_srow[NTOT];
__device__ unsigned g_nbrmask[NTOT * 32];
__device__ int   g_col_cnt[NTOT];
__device__ int   g_col_edge[NTOT * COLCAP];
__device__ int   g_edge_src[ETOT];
__device__ int   g_conn_row[ETOT];          // row in g_feat for edge attribute
__device__ float g_delta[67108864];         // entry*64 + ch
__device__ int   g_ccnt[NKT * 64];          // contributors per (kt, kl)
__device__ int   g_clist[NKT * CONCAP * 64];// [(kt*CONCAP+c)*64 + kl] = (j<<20)|entry

// ---------------- embedding body ----------------
__device__ __forceinline__ void embed_body(
    const float* __restrict__ X, int blk, int R, int Din,
    const float* __restrict__ W1, const float* __restrict__ b1,
    const float* __restrict__ W2, const float* __restrict__ b2,
    float* __restrict__ Y, float* Xs, float* Hs)
{
    int r0 = blk * 16;
    int t = threadIdx.x;
    for (int idx = t; idx < 16 * Din; idx += 128) {
        int r = idx / Din, d = idx % Din;
        Xs[r * Din + d] = (r0 + r < R) ? X[(size_t)(r0 + r) * Din + d] : 0.f;
    }
    __syncthreads();
    int lr = t >> 3;
    int c0 = (t & 7) * 8;
    float h[8];
#pragma unroll
    for (int q = 0; q < 8; q++) h[q] = b1[c0 + q];
    for (int d = 0; d < Din; d++) {
        float x = Xs[lr * Din + d];
        const float* w = W1 + d * C + c0;
#pragma unroll
        for (int q = 0; q < 8; q++) h[q] += x * w[q];
    }
#pragma unroll
    for (int q = 0; q < 8; q++) Hs[lr * C + c0 + q] = fmaxf(h[q], 0.f);
    __syncthreads();
    float y[8];
#pragma unroll
    for (int q = 0; q < 8; q++) y[q] = b2[c0 + q];
    for (int m = 0; m < C; m++) {
        float hm = Hs[lr * C + m];
        const float* w = W2 + m * C + c0;
#pragma unroll
        for (int q = 0; q < 8; q++) y[q] += hm * w[q];
    }
    if (r0 + lr < R) {
        float* yo = Y + (size_t)(r0 + lr) * C + c0;
#pragma unroll
        for (int q = 0; q < 8; q++) yo[q] = fmaxf(y[q], 0.f);
    }
}

// ---------------- launch 0: embeds + zeroing, fused ----------------
__global__ __launch_bounds__(128) void k_init(
    const float* __restrict__ node_x, const float* __restrict__ edge_x,
    const float* __restrict__ face_x,
    const float* __restrict__ nW1, const float* __restrict__ nb1,
    const float* __restrict__ nW2, const float* __restrict__ nb2,
    const float* __restrict__ eW1, const float* __restrict__ eb1,
    const float* __restrict__ eW2, const float* __restrict__ eb2,
    const float* __restrict__ fW1, const float* __restrict__ fb1,
    const float* __restrict__ fW2, const float* __restrict__ fb2)
{
    __shared__ float Xs[16 * 144];
    __shared__ float Hs[16 * C];
    int b = blockIdx.x;
    int t = threadIdx.x;
    if (b < 48) {
        embed_body(node_x, b, NNODES, 144, nW1, nb1, nW2, nb2, g_feat, Xs, Hs);
    } else if (b < 432) {
        embed_body(edge_x, b - 48, E0, 144, eW1, eb1, eW2, eb2, g_feat + NTOT * C, Xs, Hs);
    } else if (b < 448) {
        embed_body(face_x, b - 432, NFACES, 12, fW1, fb1, fW2, fb2, g_feat + NNODES * C, Xs, Hs);
    } else {
        int z = b - 448;  // 0..1023
        float4 zv = make_float4(0.f, 0.f, 0.f, 0.f);
        // adjn: 1M floats over 1024 blocks x 128 threads x 2 float4
        float4* ap = (float4*)(g_adjn) + (size_t)z * 256 + t * 2;
        ap[0] = zv; ap[1] = zv;
        if (z < 32) {
            for (int q = 0; q < 8; q++) g_nbrmask[z * 1024 + t * 8 + q] = 0u;
        } else if (z == 32) {
            for (int q = 0; q < 8; q++) g_col_cnt[t * 8 + q] = 0;
        } else if (z == 33) {
            for (int q = 0; q < 8; q++) g_ccnt[t * 8 + q] = 0;
        }
    }
}

// ---------------- launch 1: edges + diag ----------------
__global__ void k_edges(const int* __restrict__ ei, const int* __restrict__ fn) {
    int e = blockIdx.x * blockDim.x + threadIdx.x;
    if (e >= ETOT + NTOT) return;
    if (e >= ETOT) {
        int i = e - ETOT;
        atomicAdd(&g_adjn[i * NTOT + i], 1.0f);
        return;
    }
    int s, d, cr;
    if (e < E0)            { s = ei[e]; d = ei[E0 + e]; cr = NTOT + e; }
    else if (e < E0 + EF)  { int q = e - E0; int f = q / 6; s = fn[q]; d = NNODES + f; cr = NNODES + f; }
    else                   { int r = e - (E0 + EF); int rr = 1535 - r; int f = rr / 6;
                             s = NNODES + f; d = fn[rr]; cr = NNODES + f; }
    g_edge_src[e] = s;
    g_conn_row[e] = cr;
    atomicAdd(&g_adjn[s * NTOT + d], 1.0f);
    int p = atomicAdd(&g_col_cnt[d], 1);
    if (p < COLCAP) g_col_edge[d * COLCAP + p] = e;
}

// ---------------- launch 2: degree ----------------
__global__ __launch_bounds__(256) void k_deg() {
    int i = blockIdx.x;
    float s = 0.f;
    for (int j = threadIdx.x; j < NTOT; j += 256) s += g_adjn[i * NTOT + j];
    __shared__ float red[8];
#pragma unroll
    for (int o = 16; o > 0; o >>= 1) s += __shfl_down_sync(0xffffffffu, s, o);
    if ((threadIdx.x & 31) == 0) red[threadIdx.x >> 5] = s;
    __syncthreads();
    if (threadIdx.x == 0) {
        float tot = 0.f;
        for (int w = 0; w < 8; w++) tot += red[w];
        g_dinv[i] = (tot > 0.f) ? (1.f / sqrtf(tot)) : 0.f;
    }
}

// ---------------- launch 3: scale adjn + row sums + neighbor bitmask ----------------
__global__ __launch_bounds__(256) void k_scale() {
    int i = blockIdx.x;
    __shared__ float red[8];
    float di = g_dinv[i];
    float sv = 0.f;
    for (int j = threadIdx.x; j < NTOT; j += 256) {
        float v = g_adjn[i * NTOT + j];
        if (v != 0.f) {
            v *= di * g_dinv[j];
            g_adjn[i * NTOT + j] = v;
            sv += v;
            atomicOr(&g_nbrmask[i * 32 + (j >> 5)], 1u << (j & 31));
        }
    }
#pragma unroll
    for (int o = 16; o > 0; o >>= 1) sv += __shfl_down_sync(0xffffffffu, sv, o);
    if ((threadIdx.x & 31) == 0) red[threadIdx.x >> 5] = sv;
    __syncthreads();
    if (threadIdx.x == 0) {
        float tot = 0.f;
        for (int w = 0; w < 8; w++) tot += red[w];
        g_srow[i] = tot;
    }
}

// ---------------- launch 4: layer 1 deltas + contributor lists ----------------
__global__ __launch_bounds__(256) void k_layer1(
    const float* __restrict__ plW, const float* __restrict__ plb)
{
    const int kt = blockIdx.x;
    const int j  = blockIdx.y;
    const int t  = threadIdx.x;
    __shared__ float Hs[64 * 65];
    __shared__ int nf;
    __shared__ int flist[64];
    if (t == 0) nf = 0;
    __syncthreads();

    const int kl = t & 63;
    const int m0 = (t >> 6) * 16;
    const int k  = kt * 64 + kl;

    float acc[16];
    bool fl = false;
    float ajk = g_adjn[j * NTOT + k];
    if (ajk != 0.f) {
        fl = true;
        const float* na = g_feat + k * C + m0;
#pragma unroll
        for (int q = 0; q < 16; q++) acc[q] = ajk * na[q];
    } else {
#pragma unroll
        for (int q = 0; q < 16; q++) acc[q] = 0.f;
    }
    int cc = g_col_cnt[k]; if (cc > COLCAP) cc = COLCAP;
    for (int c = 0; c < cc; c++) {
        int e = g_col_edge[k * COLCAP + c];
        float a = g_adjn[j * NTOT + g_edge_src[e]];
        if (a != 0.f) {
            fl = true;
            const float4* cp = (const float4*)(g_feat + g_conn_row[e] * C + m0);
#pragma unroll
            for (int q = 0; q < 4; q++) {
                float4 v = cp[q];
                acc[4*q+0] += a * v.x; acc[4*q+1] += a * v.y;
                acc[4*q+2] += a * v.z; acc[4*q+3] += a * v.w;
            }
        }
    }
#pragma unroll
    for (int q = 0; q < 16; q++) Hs[kl * 65 + m0 + q] = acc[q];
    if ((t >> 6) == 0 && fl) { int p = atomicAdd(&nf, 1); flist[p] = kl; }
    __syncthreads();

    const int seg = j * NKT + kt;
    const int n = nf;
    const int c = t & 63;
    const float crc = fmaxf(plb[c], 0.f);
    const size_t segbase = (size_t)seg * 64 * 64;
    for (int idx = t >> 6; idx < n; idx += 4) {
        int row = flist[idx];
        float y = plb[c];
        const float* Hrow = Hs + row * 65;
#pragma unroll 16
        for (int m = 0; m < 64; m++) y += Hrow[m] * plW[m * 64 + c];
        g_delta[segbase + (size_t)idx * 64 + c] = fmaxf(y, 0.f) - crc;
        if (c == 0) {
            int entry = seg * 64 + idx;          // 20 bits
            int pos = atomicAdd(&g_ccnt[kt * 64 + row], 1);  // bounded by 1024
            g_clist[(kt * CONCAP + pos) * 64 + row] = (j << 20) | entry;
        }
    }
}

// ---------------- launch 5: layer 2 fused (gather + 3 GEMMs) ----------------
__global__ __launch_bounds__(256) void k_layer2(
    const float* __restrict__ plb0,
    const float* __restrict__ plW, const float* __restrict__ plb,
    const float* __restrict__ oW1, const float* __restrict__ ob1,
    const float* __restrict__ oW2, const float* __restrict__ ob2,
    float* __restrict__ out)
{
    __shared__ float Hs[64 * HSTR];
    __shared__ float Gs[64 * HSTR];
    __shared__ unsigned mask[32];

    const int i  = blockIdx.x;   // fastest -> concurrent blocks share kt slice
    const int kt = blockIdx.y;
    const int t  = threadIdx.x;

    if (t < 32) mask[t] = g_nbrmask[i * 32 + t];
    __syncthreads();

    // Phase A: register-resident gather, no syncs, no idle threads
    {
        const int kl  = t & 63;
        const int sub = (t >> 6) * 16;
        const float sI = g_srow[i];
        float acc[16];
#pragma unroll
        for (int q = 0; q < 16; q++) acc[q] = sI * fmaxf(plb0[sub + q], 0.f);

        const int cnt = g_ccnt[kt * 64 + kl];
        const float* __restrict__ arow = g_adjn + (size_t)i * NTOT;
        for (int c = 0; c < cnt; c++) {
            unsigned packed = (unsigned)g_clist[(kt * CONCAP + c) * 64 + kl];
            unsigned j = packed >> 20;
            if ((mask[j >> 5] >> (j & 31)) & 1u) {
                float a = arow[j];
                const float4* dp = (const float4*)(g_delta + (size_t)(packed & 0xFFFFFu) * 64 + sub);
#pragma unroll
                for (int q = 0; q < 4; q++) {
                    float4 v = dp[q];
                    acc[4*q+0] += a * v.x; acc[4*q+1] += a * v.y;
                    acc[4*q+2] += a * v.z; acc[4*q+3] += a * v.w;
                }
            }
        }
#pragma unroll
        for (int q = 0; q < 16; q++) Hs[kl * HSTR + sub + q] = acc[q];
    }
    __syncthreads();

    // Phase B: Gs = relu(Hs @ plW1 + plb1)
    {
        int r0 = (t >> 4) * 4, c0 = (t & 15) * 4;
        float y[4][4];
#pragma unroll
        for (int a = 0; a < 4; a++) { y[a][0] = plb[c0]; y[a][1] = plb[c0+1]; y[a][2] = plb[c0+2]; y[a][3] = plb[c0+3]; }
        for (int m = 0; m < 64; m++) {
            float4 w = *(const float4*)(plW + m * 64 + c0);
#pragma unroll
            for (int a = 0; a < 4; a++) {
                float av = Hs[(r0 + a) * HSTR + m];
                y[a][0] += av * w.x; y[a][1] += av * w.y; y[a][2] += av * w.z; y[a][3] += av * w.w;
            }
        }
#pragma unroll
        for (int a = 0; a < 4; a++)
#pragma unroll
            for (int b = 0; b < 4; b++) Gs[(r0 + a) * HSTR + c0 + b] = fmaxf(y[a][b], 0.f);
    }
    __syncthreads();

    // Phase C: Hs = relu(Gs @ oW1 + ob1)
    {
        int r0 = (t >> 4) * 4, c0 = (t & 15) * 4;
        float y[4][4];
#pragma unroll
        for (int a = 0; a < 4; a++) { y[a][0] = ob1[c0]; y[a][1] = ob1[c0+1]; y[a][2] = ob1[c0+2]; y[a][3] = ob1[c0+3]; }
        for (int m = 0; m < 64; m++) {
            float4 w = *(const float4*)(oW1 + m * 64 + c0);
#pragma unroll
            for (int a = 0; a < 4; a++) {
                float av = Gs[(r0 + a) * HSTR + m];
                y[a][0] += av * w.x; y[a][1] += av * w.y; y[a][2] += av * w.z; y[a][3] += av * w.w;
            }
        }
        __syncthreads();
#pragma unroll
        for (int a = 0; a < 4; a++)
#pragma unroll
            for (int b = 0; b < 4; b++) Hs[(r0 + a) * HSTR + c0 + b] = fmaxf(y[a][b], 0.f);
    }
    __syncthreads();

    // Phase D: out = Hs @ oW2 + ob2
    {
        int r0 = (t >> 3) * 2, c0 = (t & 7) * 4;
        float y[2][4];
#pragma unroll
        for (int a = 0; a < 2; a++) { y[a][0] = ob2[c0]; y[a][1] = ob2[c0+1]; y[a][2] = ob2[c0+2]; y[a][3] = ob2[c0+3]; }
        for (int m = 0; m < 64; m++) {
            float4 w = *(const float4*)(oW2 + m * 32 + c0);
#pragma unroll
            for (int a = 0; a < 2; a++) {
                float av = Hs[(r0 + a) * HSTR + m];
                y[a][0] += av * w.x; y[a][1] += av * w.y; y[a][2] += av * w.z; y[a][3] += av * w.w;
            }
        }
        size_t ob = ((size_t)i * NTOT + (size_t)kt * 64) * 32;
#pragma unroll
        for (int a = 0; a < 2; a++) {
            float4 v = make_float4(y[a][0], y[a][1], y[a][2], y[a][3]);
            *(float4*)(out + ob + (size_t)(r0 + a) * 32 + c0) = v;
        }
    }
}

// ---------------- launch ----------------
extern "C" void kernel_launch(void* const* d_in, const int* in_sizes, int n_in,
                              void* d_out, int out_size)
{
    const float* node_x = (const float*)d_in[0];
    const float* edge_x = (const float*)d_in[1];
    const float* face_x = (const float*)d_in[2];
    const float* nW1 = (const float*)d_in[3];  const float* nb1 = (const float*)d_in[4];
    const float* nW2 = (const float*)d_in[5];  const float* nb2 = (const float*)d_in[6];
    const float* eW1 = (const float*)d_in[7];  const float* eb1 = (const float*)d_in[8];
    const float* eW2 = (const float*)d_in[9];  const float* eb2 = (const float*)d_in[10];
    const float* fW1 = (const float*)d_in[11]; const float* fb1 = (const float*)d_in[12];
    const float* fW2 = (const float*)d_in[13]; const float* fb2 = (const float*)d_in[14];
    const float* oW1 = (const float*)d_in[15]; const float* ob1 = (const float*)d_in[16];
    const float* oW2 = (const float*)d_in[17]; const float* ob2 = (const float*)d_in[18];
    const float* plW = (const float*)d_in[19]; const float* plb = (const float*)d_in[20];
    const int* edge_index = (const int*)d_in[21];
    const int* face_nodes = (const int*)d_in[22];
    float* out = (float*)d_out;

    k_init<<<1472, 128>>>(node_x, edge_x, face_x, nW1, nb1, nW2, nb2,
                          eW1, eb1, eW2, eb2, fW1, fb1, fW2, fb2);
    k_edges<<<(ETOT + NTOT + 255) / 256, 256>>>(edge_index, face_nodes);
    k_deg<<<NTOT, 256>>>();
    k_scale<<<NTOT, 256>>>();
    k_layer1<<<dim3(NKT, NTOT), 256>>>(plW, plb);
    k_layer2<<<dim3(NTOT, NKT), 256>>>(plb, plW + 4096, plb + 64,
                                       oW1, ob1, oW2, ob2, out);
    (void)in_sizes; (void)n_in; (void)out_size;
}

// round 5
// speedup vs baseline: 1.5475x; 1.5475x over previous
#include <cuda_runtime.h>
#include <cstdint>

#define NNODES 768
#define NFACES 256
#define NTOT   1024
#define E0     6144
#define EF     1536
#define ETOT   9216
#define C      64
#define COLCAP 64
#define NKT    16
#define HSTR   68
#define SMEM_L2_BYTES ((64 * HSTR * 2 + 64 * 64) * 4)

// ---------------- device scratch ----------------
// unified feature table: rows [0,1024) = node_all, rows [1024,7168) = edge conn
__device__ float g_feat[(NTOT + E0) * C];
__device__ float g_adjn[NTOT * NTOT];
__device__ float g_dinv[NTOT];
__device__ float g_srow[NTOT];
__device__ int   g_row_cnt[NTOT];
__device__ int   g_row_col[NTOT * 192];
__device__ float g_row_val[NTOT * 192];
__device__ int   g_col_cnt[NTOT];
__device__ int   g_col_edge[NTOT * COLCAP];
__device__ int   g_edge_src[ETOT];
__device__ int   g_conn_row[ETOT];
__device__ float g_delta[67108864];                 // per-(j,kt) segments, 64 rows cap
__device__ unsigned char g_sidx[NTOT * NKT * 64];
__device__ int   g_scnt[NTOT * NKT];

__device__ __forceinline__ float f2lo(uint64_t v) { return __uint_as_float((unsigned)v); }
__device__ __forceinline__ float f2hi(uint64_t v) { return __uint_as_float((unsigned)(v >> 32)); }
__device__ __forceinline__ void fma2(uint64_t& d, uint64_t a, uint64_t b) {
    asm("fma.rn.f32x2 %0, %1, %2, %0;" : "+l"(d) : "l"(a), "l"(b));
}
__device__ __forceinline__ uint64_t splat2(float a) {
    uint64_t v; asm("mov.b64 %0, {%1, %1};" : "=l"(v) : "f"(a)); return v;
}

// ---------------- embedding body ----------------
__device__ __forceinline__ void embed_body(
    const float* __restrict__ X, int blk, int R, int Din,
    const float* __restrict__ W1, const float* __restrict__ b1,
    const float* __restrict__ W2, const float* __restrict__ b2,
    float* __restrict__ Y, float* Xs, float* Hs)
{
    int r0 = blk * 16;
    int t = threadIdx.x;
    for (int idx = t; idx < 16 * Din; idx += 128) {
        int r = idx / Din, d = idx % Din;
        Xs[r * Din + d] = (r0 + r < R) ? X[(size_t)(r0 + r) * Din + d] : 0.f;
    }
    __syncthreads();
    int lr = t >> 3;
    int c0 = (t & 7) * 8;
    float h[8];
#pragma unroll
    for (int q = 0; q < 8; q++) h[q] = b1[c0 + q];
    for (int d = 0; d < Din; d++) {
        float x = Xs[lr * Din + d];
        const float* w = W1 + d * C + c0;
#pragma unroll
        for (int q = 0; q < 8; q++) h[q] += x * w[q];
    }
#pragma unroll
    for (int q = 0; q < 8; q++) Hs[lr * C + c0 + q] = fmaxf(h[q], 0.f);
    __syncthreads();
    float y[8];
#pragma unroll
    for (int q = 0; q < 8; q++) y[q] = b2[c0 + q];
    for (int m = 0; m < C; m++) {
        float hm = Hs[lr * C + m];
        const float* w = W2 + m * C + c0;
#pragma unroll
        for (int q = 0; q < 8; q++) y[q] += hm * w[q];
    }
    if (r0 + lr < R) {
        float* yo = Y + (size_t)(r0 + lr) * C + c0;
#pragma unroll
        for (int q = 0; q < 8; q++) yo[q] = fmaxf(y[q], 0.f);
    }
}

// ---------------- launch 0: embeds + zeroing ----------------
__global__ __launch_bounds__(128) void k_init(
    const float* __restrict__ node_x, const float* __restrict__ edge_x,
    const float* __restrict__ face_x,
    const float* __restrict__ nW1, const float* __restrict__ nb1,
    const float* __restrict__ nW2, const float* __restrict__ nb2,
    const float* __restrict__ eW1, const float* __restrict__ eb1,
    const float* __restrict__ eW2, const float* __restrict__ eb2,
    const float* __restrict__ fW1, const float* __restrict__ fb1,
    const float* __restrict__ fW2, const float* __restrict__ fb2)
{
    __shared__ float Xs[16 * 144];
    __shared__ float Hs[16 * C];
    int b = blockIdx.x;
    int t = threadIdx.x;
    if (b < 48) {
        embed_body(node_x, b, NNODES, 144, nW1, nb1, nW2, nb2, g_feat, Xs, Hs);
    } else if (b < 432) {
        embed_body(edge_x, b - 48, E0, 144, eW1, eb1, eW2, eb2, g_feat + NTOT * C, Xs, Hs);
    } else if (b < 448) {
        embed_body(face_x, b - 432, NFACES, 12, fW1, fb1, fW2, fb2, g_feat + NNODES * C, Xs, Hs);
    } else {
        int z = b - 448;  // 0..1023
        float4 zv = make_float4(0.f, 0.f, 0.f, 0.f);
        float4* ap = (float4*)(g_adjn) + (size_t)z * 256 + t * 2;
        ap[0] = zv; ap[1] = zv;
        if (z == 0) {
            for (int q = 0; q < 8; q++) g_col_cnt[t * 8 + q] = 0;
        }
    }
}

// ---------------- launch 1: edges + diag ----------------
__global__ void k_edges(const int* __restrict__ ei, const int* __restrict__ fn) {
    int e = blockIdx.x * blockDim.x + threadIdx.x;
    if (e >= ETOT + NTOT) return;
    if (e >= ETOT) {
        int i = e - ETOT;
        atomicAdd(&g_adjn[i * NTOT + i], 1.0f);
        return;
    }
    int s, d, cr;
    if (e < E0)            { s = ei[e]; d = ei[E0 + e]; cr = NTOT + e; }
    else if (e < E0 + EF)  { int q = e - E0; int f = q / 6; s = fn[q]; d = NNODES + f; cr = NNODES + f; }
    else                   { int r = e - (E0 + EF); int rr = 1535 - r; int f = rr / 6;
                             s = NNODES + f; d = fn[rr]; cr = NNODES + f; }
    g_edge_src[e] = s;
    g_conn_row[e] = cr;
    atomicAdd(&g_adjn[s * NTOT + d], 1.0f);
    int p = atomicAdd(&g_col_cnt[d], 1);
    if (p < COLCAP) g_col_edge[d * COLCAP + p] = e;
}

// ---------------- launch 2: degree ----------------
__global__ __launch_bounds__(256) void k_deg() {
    int i = blockIdx.x;
    float s = 0.f;
    for (int j = threadIdx.x; j < NTOT; j += 256) s += g_adjn[i * NTOT + j];
    __shared__ float red[8];
#pragma unroll
    for (int o = 16; o > 0; o >>= 1) s += __shfl_down_sync(0xffffffffu, s, o);
    if ((threadIdx.x & 31) == 0) red[threadIdx.x >> 5] = s;
    __syncthreads();
    if (threadIdx.x == 0) {
        float tot = 0.f;
        for (int w = 0; w < 8; w++) tot += red[w];
        g_dinv[i] = (tot > 0.f) ? (1.f / sqrtf(tot)) : 0.f;
    }
}

// ---------------- launch 3: scale + CSR + row sums ----------------
__global__ __launch_bounds__(256) void k_scale_csr() {
    int i = blockIdx.x;
    __shared__ int cnt;
    __shared__ float red[8];
    if (threadIdx.x == 0) cnt = 0;
    __syncthreads();
    float di = g_dinv[i];
    float sv = 0.f;
    for (int j = threadIdx.x; j < NTOT; j += 256) {
        float v = g_adjn[i * NTOT + j];
        if (v != 0.f) {
            v *= di * g_dinv[j];
            g_adjn[i * NTOT + j] = v;
            sv += v;
            int p = atomicAdd(&cnt, 1);
            if (p < 192) { g_row_col[i * 192 + p] = j; g_row_val[i * 192 + p] = v; }
        }
    }
#pragma unroll
    for (int o = 16; o > 0; o >>= 1) sv += __shfl_down_sync(0xffffffffu, sv, o);
    if ((threadIdx.x & 31) == 0) red[threadIdx.x >> 5] = sv;
    __syncthreads();
    if (threadIdx.x == 0) {
        float tot = 0.f;
        for (int w = 0; w < 8; w++) tot += red[w];
        g_srow[i] = tot;
        g_row_cnt[i] = min(cnt, 192);
    }
}

// ---------------- launch 4: layer-1 delta rows ----------------
__global__ __launch_bounds__(256) void k_layer1(
    const float* __restrict__ plW, const float* __restrict__ plb)
{
    const int kt = blockIdx.x;
    const int j  = blockIdx.y;
    const int t  = threadIdx.x;
    __shared__ float Hs[64 * 65];
    __shared__ int nf;
    __shared__ int flist[64];
    if (t == 0) nf = 0;
    __syncthreads();

    const int kl = t & 63;
    const int m0 = (t >> 6) * 16;
    const int k  = kt * 64 + kl;

    float acc[16];
    bool fl = false;
    float ajk = g_adjn[j * NTOT + k];
    if (ajk != 0.f) {
        fl = true;
        const float* na = g_feat + k * C + m0;
#pragma unroll
        for (int q = 0; q < 16; q++) acc[q] = ajk * na[q];
    } else {
#pragma unroll
        for (int q = 0; q < 16; q++) acc[q] = 0.f;
    }
    int cc = g_col_cnt[k]; if (cc > COLCAP) cc = COLCAP;
    for (int c = 0; c < cc; c++) {
        int e = g_col_edge[k * COLCAP + c];
        float a = g_adjn[j * NTOT + g_edge_src[e]];
        if (a != 0.f) {
            fl = true;
            const float4* cp = (const float4*)(g_feat + g_conn_row[e] * C + m0);
#pragma unroll
            for (int q = 0; q < 4; q++) {
                float4 v = cp[q];
                acc[4*q+0] += a * v.x; acc[4*q+1] += a * v.y;
                acc[4*q+2] += a * v.z; acc[4*q+3] += a * v.w;
            }
        }
    }
#pragma unroll
    for (int q = 0; q < 16; q++) Hs[kl * 65 + m0 + q] = acc[q];
    if ((t >> 6) == 0 && fl) { int p = atomicAdd(&nf, 1); flist[p] = kl; }
    __syncthreads();

    const int seg = j * NKT + kt;
    const int n = nf;
    const int c = t & 63;
    const float crc = fmaxf(plb[c], 0.f);
    const size_t segbase = (size_t)seg * 64 * 64;
    for (int idx = t >> 6; idx < n; idx += 4) {
        int row = flist[idx];
        float y = plb[c];
        const float* Hrow = Hs + row * 65;
#pragma unroll 16
        for (int m = 0; m < 64; m++) y += Hrow[m] * plW[m * 64 + c];
        g_delta[segbase + (size_t)idx * 64 + c] = fmaxf(y, 0.f) - crc;
        if (c == 0) g_sidx[seg * 64 + idx] = (unsigned char)row;
    }
    if (t == 0) g_scnt[seg] = n;
}

// ---------------- f32x2 GEMM phases (col-pair packed W, natural layout) ----------------
__device__ __forceinline__ void loadW4(float* Ws, const float* __restrict__ W, int nf4, int t) {
    const float4* src = (const float4*)W;
    float4* dst = (float4*)Ws;
    for (int idx = t; idx < nf4; idx += 256) dst[idx] = src[idx];
}

// 64 rows x 64 cols: 4 rows x 4 cols per thread.
__device__ __forceinline__ void gemm64(
    const float* As, const float* Ws, const float* __restrict__ bias,
    float* Ps, int t, bool doRelu)
{
    const int r0 = (t >> 4) * 4;
    const int c0 = (t & 15) * 4;
    uint64_t b01 = *(const uint64_t*)(bias + c0);
    uint64_t b23 = *(const uint64_t*)(bias + c0 + 2);
    uint64_t acc[4][2];
#pragma unroll
    for (int r = 0; r < 4; r++) { acc[r][0] = b01; acc[r][1] = b23; }
#pragma unroll 8
    for (int m = 0; m < 64; m++) {
        uint64_t w0 = *(const uint64_t*)(Ws + m * 64 + c0);
        uint64_t w1 = *(const uint64_t*)(Ws + m * 64 + c0 + 2);
#pragma unroll
        for (int r = 0; r < 4; r++) {
            uint64_t aa = splat2(As[(r0 + r) * HSTR + m]);
            fma2(acc[r][0], aa, w0);
            fma2(acc[r][1], aa, w1);
        }
    }
#pragma unroll
    for (int r = 0; r < 4; r++) {
        float4 v = make_float4(f2lo(acc[r][0]), f2hi(acc[r][0]),
                               f2lo(acc[r][1]), f2hi(acc[r][1]));
        if (doRelu) {
            v.x = fmaxf(v.x, 0.f); v.y = fmaxf(v.y, 0.f);
            v.z = fmaxf(v.z, 0.f); v.w = fmaxf(v.w, 0.f);
        }
        *(float4*)(Ps + (r0 + r) * HSTR + c0) = v;
    }
}

// 64 rows x 32 cols -> global: 2 rows x 4 cols per thread.
__device__ __forceinline__ void gemm32_out(
    const float* As, const float* Ws, const float* __restrict__ bias,
    float* outG, int t)
{
    const int r0 = (t >> 3) * 2;
    const int c0 = (t & 7) * 4;
    uint64_t b01 = *(const uint64_t*)(bias + c0);
    uint64_t b23 = *(const uint64_t*)(bias + c0 + 2);
    uint64_t acc[2][2];
#pragma unroll
    for (int r = 0; r < 2; r++) { acc[r][0] = b01; acc[r][1] = b23; }
#pragma unroll 8
    for (int m = 0; m < 64; m++) {
        uint64_t w0 = *(const uint64_t*)(Ws + m * 32 + c0);
        uint64_t w1 = *(const uint64_t*)(Ws + m * 32 + c0 + 2);
#pragma unroll
        for (int r = 0; r < 2; r++) {
            uint64_t aa = splat2(As[(r0 + r) * HSTR + m]);
            fma2(acc[r][0], aa, w0);
            fma2(acc[r][1], aa, w1);
        }
    }
#pragma unroll
    for (int r = 0; r < 2; r++) {
        float4 v = make_float4(f2lo(acc[r][0]), f2hi(acc[r][0]),
                               f2lo(acc[r][1]), f2hi(acc[r][1]));
        *(float4*)(outG + (size_t)(r0 + r) * 32 + c0) = v;
    }
}

// ---------------- launch 5: layer 2 fused ----------------
__global__ __launch_bounds__(256) void k_layer2(
    const float* __restrict__ plb0,
    const float* __restrict__ plW, const float* __restrict__ plb,
    const float* __restrict__ oW1, const float* __restrict__ ob1,
    const float* __restrict__ oW2, const float* __restrict__ ob2,
    float* __restrict__ out)
{
    extern __shared__ float smem[];
    float* Hs = smem;                  // [64][HSTR]
    float* Gs = smem + 64 * HSTR;      // [64][HSTR]
    float* Ws = smem + 128 * HSTR;     // [64][64]

    const int i  = blockIdx.x;   // fastest -> concurrent blocks share kt slice in L2
    const int kt = blockIdx.y;
    const int t  = threadIdx.x;

    // Phase A: Hs[k,:] = s_i*cr + sum_{j in nbr(i)} a_ij * delta(j,k,:)
    {
        const int kl = t & 63;
        const int m0 = (t >> 6) * 16;
        const float sI = g_srow[i];
#pragma unroll
        for (int q = 0; q < 16; q++)
            Hs[kl * HSTR + m0 + q] = sI * fmaxf(plb0[m0 + q], 0.f);
        __syncthreads();

        const int rn = g_row_cnt[i];
        const int*   rc = g_row_col + i * 192;
        const float* rv = g_row_val + i * 192;
        const int p   = t >> 2;
        const int sub = (t & 3) * 16;
        for (int r = 0; r < rn; r++) {
            int j = rc[r];
            float a = rv[r];
            int seg = j * NKT + kt;
            int cnt = g_scnt[seg];
            if (p < cnt) {
                int klq = g_sidx[seg * 64 + p];
                const float4* dp = (const float4*)(g_delta + ((size_t)seg * 64 + p) * 64 + sub);
                float* h = Hs + klq * HSTR + sub;
#pragma unroll
                for (int q = 0; q < 4; q++) {
                    float4 v = dp[q];
                    h[4*q+0] += a * v.x; h[4*q+1] += a * v.y;
                    h[4*q+2] += a * v.z; h[4*q+3] += a * v.w;
                }
            }
            __syncthreads();
        }
    }

    // Phase B: Gs = relu(Hs @ plW1 + plb1)
    loadW4(Ws, plW, 1024, t);
    __syncthreads();
    gemm64(Hs, Ws, plb, Gs, t, true);
    __syncthreads();

    // Phase C: Hs = relu(Gs @ oW1 + ob1)
    loadW4(Ws, oW1, 1024, t);
    __syncthreads();
    gemm64(Gs, Ws, ob1, Hs, t, true);
    __syncthreads();

    // Phase D: out = Hs @ oW2 + ob2
    loadW4(Ws, oW2, 512, t);
    __syncthreads();
    gemm32_out(Hs, Ws, ob2, out + ((size_t)i * NTOT + (size_t)kt * 64) * 32, t);
}

// ---------------- launch ----------------
extern "C" void kernel_launch(void* const* d_in, const int* in_sizes, int n_in,
                              void* d_out, int out_size)
{
    const float* node_x = (const float*)d_in[0];
    const float* edge_x = (const float*)d_in[1];
    const float* face_x = (const float*)d_in[2];
    const float* nW1 = (const float*)d_in[3];  const float* nb1 = (const float*)d_in[4];
    const float* nW2 = (const float*)d_in[5];  const float* nb2 = (const float*)d_in[6];
    const float* eW1 = (const float*)d_in[7];  const float* eb1 = (const float*)d_in[8];
    const float* eW2 = (const float*)d_in[9];  const float* eb2 = (const float*)d_in[10];
    const float* fW1 = (const float*)d_in[11]; const float* fb1 = (const float*)d_in[12];
    const float* fW2 = (const float*)d_in[13]; const float* fb2 = (const float*)d_in[14];
    const float* oW1 = (const float*)d_in[15]; const float* ob1 = (const float*)d_in[16];
    const float* oW2 = (const float*)d_in[17]; const float* ob2 = (const float*)d_in[18];
    const float* plW = (const float*)d_in[19]; const float* plb = (const float*)d_in[20];
    const int* edge_index = (const int*)d_in[21];
    const int* face_nodes = (const int*)d_in[22];
    float* out = (float*)d_out;

    cudaFuncSetAttribute(k_layer2, cudaFuncAttributeMaxDynamicSharedMemorySize, SMEM_L2_BYTES);

    k_init<<<1472, 128>>>(node_x, edge_x, face_x, nW1, nb1, nW2, nb2,
                          eW1, eb1, eW2, eb2, fW1, fb1, fW2, fb2);
    k_edges<<<(ETOT + NTOT + 255) / 256, 256>>>(edge_index, face_nodes);
    k_deg<<<NTOT, 256>>>();
    k_scale_csr<<<NTOT, 256>>>();
    k_layer1<<<dim3(NKT, NTOT), 256>>>(plW, plb);
    k_layer2<<<dim3(NTOT, NKT), 256, SMEM_L2_BYTES>>>(plb, plW + 4096, plb + 64,
                                                      oW1, ob1, oW2, ob2, out);
    (void)in_sizes; (void)n_in; (void)out_size;
}

// round 6
// speedup vs baseline: 1.7880x; 1.1554x over previous
#include <cuda_runtime.h>
#include <cstdint>

#define NNODES 768
#define NFACES 256
#define NTOT   1024
#define E0     6144
#define EF     1536
#define ETOT   9216
#define C      64
#define COLCAP 64
#define NKT    16
#define HSTR   68
#define SMEM_L2_BYTES ((64 * HSTR * 2 + 64 * 64) * 4)

// ---------------- device scratch ----------------
__device__ float g_feat[(NTOT + E0) * C];   // [0,1024): node_all; [1024,7168): edge conn
__device__ float g_adjn[NTOT * NTOT];
__device__ int   g_outcnt[NTOT];
__device__ float g_srow[NTOT];
__device__ int   g_row_cnt[NTOT];
__device__ int   g_row_col[NTOT * 192];
__device__ float g_row_val[NTOT * 192];
__device__ int   g_col_cnt[NTOT];
__device__ int   g_col_sc[NTOT * COLCAP];   // (src<<13)|conn_row
__device__ float g_delta[67108864];
__device__ unsigned char g_sidx[NTOT * NKT * 64];
__device__ int   g_scnt[NTOT * NKT];

__device__ __forceinline__ float f2lo(uint64_t v) { return __uint_as_float((unsigned)v); }
__device__ __forceinline__ float f2hi(uint64_t v) { return __uint_as_float((unsigned)(v >> 32)); }
__device__ __forceinline__ void fma2(uint64_t& d, uint64_t a, uint64_t b) {
    asm("fma.rn.f32x2 %0, %1, %2, %0;" : "+l"(d) : "l"(a), "l"(b));
}
__device__ __forceinline__ uint64_t splat2(float a) {
    uint64_t v; asm("mov.b64 %0, {%1, %1};" : "=l"(v) : "f"(a)); return v;
}

// ---------------- embedding body ----------------
__device__ __forceinline__ void embed_body(
    const float* __restrict__ X, int blk, int R, int Din,
    const float* __restrict__ W1, const float* __restrict__ b1,
    const float* __restrict__ W2, const float* __restrict__ b2,
    float* __restrict__ Y, float* Xs, float* Hs)
{
    int r0 = blk * 16;
    int t = threadIdx.x;
    for (int idx = t; idx < 16 * Din; idx += 128) {
        int r = idx / Din, d = idx % Din;
        Xs[r * Din + d] = (r0 + r < R) ? X[(size_t)(r0 + r) * Din + d] : 0.f;
    }
    __syncthreads();
    int lr = t >> 3;
    int c0 = (t & 7) * 8;
    float h[8];
#pragma unroll
    for (int q = 0; q < 8; q++) h[q] = b1[c0 + q];
    for (int d = 0; d < Din; d++) {
        float x = Xs[lr * Din + d];
        const float* w = W1 + d * C + c0;
#pragma unroll
        for (int q = 0; q < 8; q++) h[q] += x * w[q];
    }
#pragma unroll
    for (int q = 0; q < 8; q++) Hs[lr * C + c0 + q] = fmaxf(h[q], 0.f);
    __syncthreads();
    float y[8];
#pragma unroll
    for (int q = 0; q < 8; q++) y[q] = b2[c0 + q];
    for (int m = 0; m < C; m++) {
        float hm = Hs[lr * C + m];
        const float* w = W2 + m * C + c0;
#pragma unroll
        for (int q = 0; q < 8; q++) y[q] += hm * w[q];
    }
    if (r0 + lr < R) {
        float* yo = Y + (size_t)(r0 + lr) * C + c0;
#pragma unroll
        for (int q = 0; q < 8; q++) yo[q] = fmaxf(y[q], 0.f);
    }
}

// ---------------- launch 1: embeds + zeroing ----------------
__global__ __launch_bounds__(128) void k_init(
    const float* __restrict__ node_x, const float* __restrict__ edge_x,
    const float* __restrict__ face_x,
    const float* __restrict__ nW1, const float* __restrict__ nb1,
    const float* __restrict__ nW2, const float* __restrict__ nb2,
    const float* __restrict__ eW1, const float* __restrict__ eb1,
    const float* __restrict__ eW2, const float* __restrict__ eb2,
    const float* __restrict__ fW1, const float* __restrict__ fb1,
    const float* __restrict__ fW2, const float* __restrict__ fb2)
{
    __shared__ float Xs[16 * 144];
    __shared__ float Hs[16 * C];
    int b = blockIdx.x;
    int t = threadIdx.x;
    if (b < 48) {
        embed_body(node_x, b, NNODES, 144, nW1, nb1, nW2, nb2, g_feat, Xs, Hs);
    } else if (b < 432) {
        embed_body(edge_x, b - 48, E0, 144, eW1, eb1, eW2, eb2, g_feat + NTOT * C, Xs, Hs);
    } else if (b < 448) {
        embed_body(face_x, b - 432, NFACES, 12, fW1, fb1, fW2, fb2, g_feat + NNODES * C, Xs, Hs);
    } else {
        int z = b - 448;  // 0..1023
        float4 zv = make_float4(0.f, 0.f, 0.f, 0.f);
        float4* ap = (float4*)(g_adjn) + (size_t)z * 256 + t * 2;
        ap[0] = zv; ap[1] = zv;
        if (z == 0) {
            for (int q = 0; q < 8; q++) g_col_cnt[t * 8 + q] = 0;
        } else if (z == 1) {
            for (int q = 0; q < 8; q++) g_outcnt[t * 8 + q] = 0;
        }
    }
}

// ---------------- launch 2: edges + diag + out-degree counts ----------------
__global__ void k_edges(const int* __restrict__ ei, const int* __restrict__ fn) {
    int e = blockIdx.x * blockDim.x + threadIdx.x;
    if (e >= ETOT + NTOT) return;
    if (e >= ETOT) {
        int i = e - ETOT;
        atomicAdd(&g_adjn[i * NTOT + i], 1.0f);
        return;
    }
    int s, d, cr;
    if (e < E0)            { s = ei[e]; d = ei[E0 + e]; cr = NTOT + e; }
    else if (e < E0 + EF)  { int q = e - E0; int f = q / 6; s = fn[q]; d = NNODES + f; cr = NNODES + f; }
    else                   { int r = e - (E0 + EF); int rr = 1535 - r; int f = rr / 6;
                             s = NNODES + f; d = fn[rr]; cr = NNODES + f; }
    atomicAdd(&g_adjn[s * NTOT + d], 1.0f);
    atomicAdd(&g_outcnt[s], 1);
    int p = atomicAdd(&g_col_cnt[d], 1);
    if (p < COLCAP) g_col_sc[d * COLCAP + p] = (s << 13) | cr;
}

// ---------------- launch 3: scale + CSR + row sums (deg = outcnt + 1) ----------------
__global__ __launch_bounds__(256) void k_scale_csr() {
    int i = blockIdx.x;
    __shared__ int cnt;
    __shared__ float red[8];
    if (threadIdx.x == 0) cnt = 0;
    __syncthreads();
    float di = 1.f / sqrtf(1.f + (float)g_outcnt[i]);
    float sv = 0.f;
    for (int j = threadIdx.x; j < NTOT; j += 256) {
        float v = g_adjn[i * NTOT + j];
        if (v != 0.f) {
            float dj = 1.f / sqrtf(1.f + (float)g_outcnt[j]);
            v *= di * dj;
            g_adjn[i * NTOT + j] = v;
            sv += v;
            int p = atomicAdd(&cnt, 1);
            if (p < 192) { g_row_col[i * 192 + p] = j; g_row_val[i * 192 + p] = v; }
        }
    }
#pragma unroll
    for (int o = 16; o > 0; o >>= 1) sv += __shfl_down_sync(0xffffffffu, sv, o);
    if ((threadIdx.x & 31) == 0) red[threadIdx.x >> 5] = sv;
    __syncthreads();
    if (threadIdx.x == 0) {
        float tot = 0.f;
        for (int w = 0; w < 8; w++) tot += red[w];
        g_srow[i] = tot;
        g_row_cnt[i] = min(cnt, 192);
    }
}

// ---------------- launch 4: layer-1 delta rows (shared-staged scan) ----------------
__global__ __launch_bounds__(256) void k_layer1(
    const float* __restrict__ plW, const float* __restrict__ plb)
{
    const int kt = blockIdx.x;
    const int j  = blockIdx.y;
    const int t  = threadIdx.x;
    __shared__ float Hs[64 * 65];
    __shared__ float sAdj[NTOT];
    __shared__ int   sColsc[64 * 65];   // padded stride 65 -> conflict-free column scans
    __shared__ int   sCnt[64];
    __shared__ int nf;
    __shared__ int flist[64];
    if (t == 0) nf = 0;

    // stage adjn row j (coalesced, 256 x float4)
    {
        const float4* src = (const float4*)(g_adjn + (size_t)j * NTOT);
        ((float4*)sAdj)[t] = src[t];
    }
    // stage packed col lists for this kt tile (64 cols x 64 cap), re-padded to stride 65
    {
        const int4* src = (const int4*)(g_col_sc + kt * 64 * COLCAP);
#pragma unroll
        for (int q = 0; q < 4; q++) {
            int idx4 = t + q * 256;               // 0..1023 int4s
            int4 v = src[idx4];
            int kl = idx4 >> 4;                   // 16 int4 per column
            int c  = (idx4 & 15) * 4;
            int* dst = sColsc + kl * 65 + c;
            dst[0] = v.x; dst[1] = v.y; dst[2] = v.z; dst[3] = v.w;
        }
    }
    if (t < 64) sCnt[t] = min(g_col_cnt[kt * 64 + t], COLCAP);
    __syncthreads();

    const int kl = t & 63;
    const int m0 = (t >> 6) * 16;
    const int k  = kt * 64 + kl;

    float acc[16];
    bool fl = false;
    float ajk = sAdj[k];
    if (ajk != 0.f) {
        fl = true;
        const float* na = g_feat + k * C + m0;
#pragma unroll
        for (int q = 0; q < 16; q++) acc[q] = ajk * na[q];
    } else {
#pragma unroll
        for (int q = 0; q < 16; q++) acc[q] = 0.f;
    }
    const int cc = sCnt[kl];
    const int* lst = sColsc + kl * 65;
    for (int c = 0; c < cc; c++) {
        int packed = lst[c];
        float a = sAdj[packed >> 13];
        if (a != 0.f) {
            fl = true;
            const float4* cp = (const float4*)(g_feat + (packed & 8191) * C + m0);
#pragma unroll
            for (int q = 0; q < 4; q++) {
                float4 v = cp[q];
                acc[4*q+0] += a * v.x; acc[4*q+1] += a * v.y;
                acc[4*q+2] += a * v.z; acc[4*q+3] += a * v.w;
            }
        }
    }
#pragma unroll
    for (int q = 0; q < 16; q++) Hs[kl * 65 + m0 + q] = acc[q];
    if ((t >> 6) == 0 && fl) { int p = atomicAdd(&nf, 1); flist[p] = kl; }
    __syncthreads();

    const int seg = j * NKT + kt;
    const int n = nf;
    const int c = t & 63;
    const float crc = fmaxf(plb[c], 0.f);
    const size_t segbase = (size_t)seg * 64 * 64;
    for (int idx = t >> 6; idx < n; idx += 4) {
        int row = flist[idx];
        float y = plb[c];
        const float* Hrow = Hs + row * 65;
#pragma unroll 16
        for (int m = 0; m < 64; m++) y += Hrow[m] * plW[m * 64 + c];
        g_delta[segbase + (size_t)idx * 64 + c] = fmaxf(y, 0.f) - crc;
        if (c == 0) g_sidx[seg * 64 + idx] = (unsigned char)row;
    }
    if (t == 0) g_scnt[seg] = n;
}

// ---------------- f32x2 GEMM phases: k-unrolled x4, float4 As broadcast ----------------
__device__ __forceinline__ void loadW4(float* Ws, const float* __restrict__ W, int nf4, int t) {
    const float4* src = (const float4*)W;
    float4* dst = (float4*)Ws;
    for (int idx = t; idx < nf4; idx += 256) dst[idx] = src[idx];
}

__device__ __forceinline__ void gemm64(
    const float* As, const float* Ws, const float* __restrict__ bias,
    float* Ps, int t, bool doRelu)
{
    const int r0 = (t >> 4) * 4;
    const int c0 = (t & 15) * 4;
    uint64_t b01 = *(const uint64_t*)(bias + c0);
    uint64_t b23 = *(const uint64_t*)(bias + c0 + 2);
    uint64_t acc[4][2];
#pragma unroll
    for (int r = 0; r < 4; r++) { acc[r][0] = b01; acc[r][1] = b23; }
#pragma unroll 4
    for (int m4 = 0; m4 < 64; m4 += 4) {
        float4 a4[4];
#pragma unroll
        for (int r = 0; r < 4; r++) a4[r] = *(const float4*)(As + (r0 + r) * HSTR + m4);
#pragma unroll
        for (int kk = 0; kk < 4; kk++) {
            uint64_t w0 = *(const uint64_t*)(Ws + (m4 + kk) * 64 + c0);
            uint64_t w1 = *(const uint64_t*)(Ws + (m4 + kk) * 64 + c0 + 2);
#pragma unroll
            for (int r = 0; r < 4; r++) {
                float av = (kk == 0) ? a4[r].x : (kk == 1) ? a4[r].y : (kk == 2) ? a4[r].z : a4[r].w;
                uint64_t aa = splat2(av);
                fma2(acc[r][0], aa, w0);
                fma2(acc[r][1], aa, w1);
            }
        }
    }
#pragma unroll
    for (int r = 0; r < 4; r++) {
        float4 v = make_float4(f2lo(acc[r][0]), f2hi(acc[r][0]),
                               f2lo(acc[r][1]), f2hi(acc[r][1]));
        if (doRelu) {
            v.x = fmaxf(v.x, 0.f); v.y = fmaxf(v.y, 0.f);
            v.z = fmaxf(v.z, 0.f); v.w = fmaxf(v.w, 0.f);
        }
        *(float4*)(Ps + (r0 + r) * HSTR + c0) = v;
    }
}

__device__ __forceinline__ void gemm32_out(
    const float* As, const float* Ws, const float* __restrict__ bias,
    float* outG, int t)
{
    const int r0 = (t >> 3) * 2;
    const int c0 = (t & 7) * 4;
    uint64_t b01 = *(const uint64_t*)(bias + c0);
    uint64_t b23 = *(const uint64_t*)(bias + c0 + 2);
    uint64_t acc[2][2];
#pragma unroll
    for (int r = 0; r < 2; r++) { acc[r][0] = b01; acc[r][1] = b23; }
#pragma unroll 4
    for (int m4 = 0; m4 < 64; m4 += 4) {
        float4 a4[2];
#pragma unroll
        for (int r = 0; r < 2; r++) a4[r] = *(const float4*)(As + (r0 + r) * HSTR + m4);
#pragma unroll
        for (int kk = 0; kk < 4; kk++) {
            uint64_t w0 = *(const uint64_t*)(Ws + (m4 + kk) * 32 + c0);
            uint64_t w1 = *(const uint64_t*)(Ws + (m4 + kk) * 32 + c0 + 2);
#pragma unroll
            for (int r = 0; r < 2; r++) {
                float av = (kk == 0) ? a4[r].x : (kk == 1) ? a4[r].y : (kk == 2) ? a4[r].z : a4[r].w;
                uint64_t aa = splat2(av);
                fma2(acc[r][0], aa, w0);
                fma2(acc[r][1], aa, w1);
            }
        }
    }
#pragma unroll
    for (int r = 0; r < 2; r++) {
        float4 v = make_float4(f2lo(acc[r][0]), f2hi(acc[r][0]),
                               f2lo(acc[r][1]), f2hi(acc[r][1]));
        *(float4*)(outG + (size_t)(r0 + r) * 32 + c0) = v;
    }
}

// ---------------- launch 5: layer 2 fused ----------------
__global__ __launch_bounds__(256) void k_layer2(
    const float* __restrict__ plb0,
    const float* __restrict__ plW, const float* __restrict__ plb,
    const float* __restrict__ oW1, const float* __restrict__ ob1,
    const float* __restrict__ oW2, const float* __restrict__ ob2,
    float* __restrict__ out)
{
    extern __shared__ float smem[];
    float* Hs = smem;                  // [64][HSTR]
    float* Gs = smem + 64 * HSTR;      // [64][HSTR]
    float* Ws = smem + 128 * HSTR;     // [64][64]

    const int i  = blockIdx.x;
    const int kt = blockIdx.y;
    const int t  = threadIdx.x;

    // Phase A: Hs[k,:] = s_i*cr + sum_{j in nbr(i)} a_ij * delta(j,k,:)
    {
        const int kl = t & 63;
        const int m0 = (t >> 6) * 16;
        const float sI = g_srow[i];
#pragma unroll
        for (int q = 0; q < 16; q++)
            Hs[kl * HSTR + m0 + q] = sI * fmaxf(plb0[m0 + q], 0.f);
        __syncthreads();

        const int rn = g_row_cnt[i];
        const int*   rc = g_row_col + i * 192;
        const float* rv = g_row_val + i * 192;
        const int p   = t >> 2;
        const int sub = (t & 3) * 16;
        for (int r = 0; r < rn; r++) {
            int j = rc[r];
            float a = rv[r];
            int seg = j * NKT + kt;
            int cnt = g_scnt[seg];
            if (p < cnt) {
                int klq = g_sidx[seg * 64 + p];
                const float4* dp = (const float4*)(g_delta + ((size_t)seg * 64 + p) * 64 + sub);
                float* h = Hs + klq * HSTR + sub;
#pragma unroll
                for (int q = 0; q < 4; q++) {
                    float4 v = dp[q];
                    h[4*q+0] += a * v.x; h[4*q+1] += a * v.y;
                    h[4*q+2] += a * v.z; h[4*q+3] += a * v.w;
                }
            }
            __syncthreads();
        }
    }

    // Phase B: Gs = relu(Hs @ plW1 + plb1)
    loadW4(Ws, plW, 1024, t);
    __syncthreads();
    gemm64(Hs, Ws, plb, Gs, t, true);
    __syncthreads();

    // Phase C: Hs = relu(Gs @ oW1 + ob1)
    loadW4(Ws, oW1, 1024, t);
    __syncthreads();
    gemm64(Gs, Ws, ob1, Hs, t, true);
    __syncthreads();

    // Phase D: out = Hs @ oW2 + ob2
    loadW4(Ws, oW2, 512, t);
    __syncthreads();
    gemm32_out(Hs, Ws, ob2, out + ((size_t)i * NTOT + (size_t)kt * 64) * 32, t);
}

// ---------------- launch ----------------
extern "C" void kernel_launch(void* const* d_in, const int* in_sizes, int n_in,
                              void* d_out, int out_size)
{
    const float* node_x = (const float*)d_in[0];
    const float* edge_x = (const float*)d_in[1];
    const float* face_x = (const float*)d_in[2];
    const float* nW1 = (const float*)d_in[3];  const float* nb1 = (const float*)d_in[4];
    const float* nW2 = (const float*)d_in[5];  const float* nb2 = (const float*)d_in[6];
    const float* eW1 = (const float*)d_in[7];  const float* eb1 = (const float*)d_in[8];
    const float* eW2 = (const float*)d_in[9];  const float* eb2 = (const float*)d_in[10];
    const float* fW1 = (const float*)d_in[11]; const float* fb1 = (const float*)d_in[12];
    const float* fW2 = (const float*)d_in[13]; const float* fb2 = (const float*)d_in[14];
    const float* oW1 = (const float*)d_in[15]; const float* ob1 = (const float*)d_in[16];
    const float* oW2 = (const float*)d_in[17]; const float* ob2 = (const float*)d_in[18];
    const float* plW = (const float*)d_in[19]; const float* plb = (const float*)d_in[20];
    const int* edge_index = (const int*)d_in[21];
    const int* face_nodes = (const int*)d_in[22];
    float* out = (float*)d_out;

    cudaFuncSetAttribute(k_layer2, cudaFuncAttributeMaxDynamicSharedMemorySize, SMEM_L2_BYTES);

    k_init<<<1472, 128>>>(node_x, edge_x, face_x, nW1, nb1, nW2, nb2,
                          eW1, eb1, eW2, eb2, fW1, fb1, fW2, fb2);
    k_edges<<<(ETOT + NTOT + 255) / 256, 256>>>(edge_index, face_nodes);
    k_scale_csr<<<NTOT, 256>>>();
    k_layer1<<<dim3(NKT, NTOT), 256>>>(plW, plb);
    k_layer2<<<dim3(NTOT, NKT), 256, SMEM_L2_BYTES>>>(plb, plW + 4096, plb + 64,
                                                      oW1, ob1, oW2, ob2, out);
    (void)in_sizes; (void)n_in; (void)out_size;
}